// round 10
// baseline (speedup 1.0000x reference)
#include <cuda_runtime.h>
#include <cstdint>

// Problem constants (fixed by the dataset)
#define NPTS   120000
#define DD     41
#define HH     1024
#define WW     1024
#define HBITS  18
#define HSZ    (1 << HBITS)
#define HMASK  (HSZ - 1)
#define MAXP   (NPTS * 26)
#define TILE   128

// ---------------- static device scratch (no allocations allowed) ----------------
__device__ int   g_hkey[HSZ];
__device__ int   g_hval[HSZ];
__device__ int   g_npairs;
__device__ int2  g_pairs[MAXP];
__device__ float g_bufA[NPTS * 64];
__device__ float g_bufB[NPTS * 64];

// ---------------- f32x2 packed math ----------------
__device__ __forceinline__ unsigned long long f2fma(unsigned long long a,
                                                    unsigned long long b,
                                                    unsigned long long c) {
    unsigned long long d;
    asm("fma.rn.f32x2 %0, %1, %2, %3;" : "=l"(d) : "l"(a), "l"(b), "l"(c));
    return d;
}
__device__ __forceinline__ unsigned long long f2splat(float x) {
    unsigned long long d;
    asm("mov.b64 %0, {%1, %1};" : "=l"(d) : "r"(__float_as_int(x)));
    return d;
}

__device__ __forceinline__ unsigned hashf(int key) {
    return ((unsigned)key * 2654435761u) >> (32 - HBITS);
}

// ---------------- rulebook build ----------------
__global__ void k_clear() {
    int i = blockIdx.x * blockDim.x + threadIdx.x;
    if (i < HSZ / 4) ((int4*)g_hkey)[i] = make_int4(-1, -1, -1, -1);
    if (i == 0) g_npairs = 0;
}

__global__ void k_insert(const int* __restrict__ coors, int n) {
    int i = blockIdx.x * blockDim.x + threadIdx.x;
    if (i >= n) return;
    int4 c = ((const int4*)coors)[i];
    int key = ((c.x * DD + c.y) * HH + c.z) * WW + c.w;
    unsigned s = hashf(key) & HMASK;
    while (true) {
        int old = atomicCAS(&g_hkey[s], -1, key);
        if (old == -1) { g_hval[s] = i; break; }
        s = (s + 1) & HMASK;
    }
}

// one thread per point, loop over 26 non-center taps (center folded into GEMM)
__global__ void k_pairs(const int* __restrict__ coors, int n) {
    int i = blockIdx.x * blockDim.x + threadIdx.x;
    if (i >= n) return;
    int4 c = ((const int4*)coors)[i];
    #pragma unroll
    for (int k = 0; k < 27; k++) {
        if (k == 13) continue;
        int dz = k / 9 - 1, dy = (k / 3) % 3 - 1, dx = k % 3 - 1;
        int z = c.y + dz, y = c.z + dy, x = c.w + dx;
        if (z < 0 || z >= DD || y < 0 || y >= HH || x < 0 || x >= WW) continue;
        int key = ((c.x * DD + z) * HH + y) * WW + x;
        unsigned s = hashf(key) & HMASK;
        int j = -1;
        while (true) {
            int kk = g_hkey[s];
            if (kk == key) { j = g_hval[s]; break; }
            if (kk == -1) break;
            s = (s + 1) & HMASK;
        }
        if (j < 0) continue;
        int slot = atomicAdd(&g_npairs, 1);
        if (slot < MAXP) g_pairs[slot] = make_int2(i, (j << 5) | k);
    }
}

// ---------------- dense center GEMM:  y[N,64] = x[N,64] @ Wc[64,64] ----------------
// 128 threads, 128-point tile. Thread (pg=tid>>2, cg=tid&3) computes 4 points
// (pg*4..pg*4+3) x 16 couts (cg*16..cg*16+15) = 64 fp32 accumulators (32 f32x2).
// x staged transposed sxT[cin][point] with XOR-granule swizzle -> LDS.128 of 4
// consecutive points, conflict-free. W staged granule-permuted -> lanes cg=0..3
// read 4 consecutive 16B granules, conflict-free. FMA-pipe bound by design:
// per warp per cin: 5 LDS.128 + 4 MOV64 vs 32 FFMA2.
__global__ __launch_bounds__(128, 4)
void k_gemm(const float* __restrict__ xg, const float* __restrict__ Wc,
            float* __restrict__ yg, int n) {
    __shared__ float sxT[64 * 128];   // 32KB: [cin][swizzled point]
    __shared__ float sw[64 * 64];     // 16KB: [cin][granule-permuted couts]

    int tid = threadIdx.x;
    long base = (long)blockIdx.x * TILE;

    // Stage W with granule permutation: source granule (cg,q4) -> dst q4*4+cg.
    const float4* W4 = (const float4*)Wc;
    float4* sw4 = (float4*)sw;
    #pragma unroll
    for (int m = 0; m < 8; m++) {
        int lin = m * 128 + tid;                 // 1024 float4s
        int cin = lin >> 4, gsrc = lin & 15;     // gsrc = cg*4 + q4
        int gdst = (gsrc & 3) * 4 + (gsrc >> 2); // -> q4*4 + cg
        sw4[cin * 16 + gdst] = W4[lin];
    }

    // Stage x transposed + swizzled: sxT[cin][4*((p>>2)^(cin&31)) + (p&3)]
    const float4* xg4 = (const float4*)xg;
    #pragma unroll
    for (int m = 0; m < 16; m++) {
        int lin = m * 128 + tid;                 // 2048 float4s
        int p = lin >> 4, c4 = lin & 15;
        float4 v = make_float4(0.f, 0.f, 0.f, 0.f);
        if (base + p < n) v = xg4[(base + p) * 16 + c4];
        float comp[4] = {v.x, v.y, v.z, v.w};
        #pragma unroll
        for (int i = 0; i < 4; i++) {
            int cin = 4 * c4 + i;
            int g = (p >> 2) ^ (cin & 31);
            sxT[cin * 128 + 4 * g + (p & 3)] = comp[i];
        }
    }
    __syncthreads();

    int pg = tid >> 2, cg = tid & 3;
    unsigned long long acc[4][8];
    #pragma unroll
    for (int j = 0; j < 4; j++)
        #pragma unroll
        for (int q = 0; q < 8; q++) acc[j][q] = 0ULL;

    const float4* sxT4 = (const float4*)sxT;
    const ulonglong2* swp = (const ulonglong2*)sw;

    #pragma unroll 8
    for (int cin = 0; cin < 64; cin++) {
        float4 xv = sxT4[cin * 32 + (pg ^ (cin & 31))];   // 4 points, this cin
        unsigned long long s0 = f2splat(xv.x);
        unsigned long long s1 = f2splat(xv.y);
        unsigned long long s2 = f2splat(xv.z);
        unsigned long long s3 = f2splat(xv.w);
        #pragma unroll
        for (int q4 = 0; q4 < 4; q4++) {
            ulonglong2 w = swp[cin * 16 + q4 * 4 + cg];   // couts cg*16+4q4..+3
            acc[0][2 * q4]     = f2fma(s0, w.x, acc[0][2 * q4]);
            acc[0][2 * q4 + 1] = f2fma(s0, w.y, acc[0][2 * q4 + 1]);
            acc[1][2 * q4]     = f2fma(s1, w.x, acc[1][2 * q4]);
            acc[1][2 * q4 + 1] = f2fma(s1, w.y, acc[1][2 * q4 + 1]);
            acc[2][2 * q4]     = f2fma(s2, w.x, acc[2][2 * q4]);
            acc[2][2 * q4 + 1] = f2fma(s2, w.y, acc[2][2 * q4 + 1]);
            acc[3][2 * q4]     = f2fma(s3, w.x, acc[3][2 * q4]);
            acc[3][2 * q4 + 1] = f2fma(s3, w.y, acc[3][2 * q4 + 1]);
        }
    }

    // Epilogue: 4 points x 16 couts, 4 STG.128 per point, coalesced across cg.
    #pragma unroll
    for (int j = 0; j < 4; j++) {
        long p = base + 4 * pg + j;
        if (p >= n) continue;
        ulonglong2* yrow = (ulonglong2*)(yg + p * 64 + cg * 16);
        #pragma unroll
        for (int q4 = 0; q4 < 4; q4++) {
            ulonglong2 o;
            o.x = acc[j][2 * q4];
            o.y = acc[j][2 * q4 + 1];
            yrow[q4] = o;
        }
    }
}

// ---------------- sparse correction: out[i] += x[j] @ W[l,k] per pair ----------
__global__ void k_apply_pairs(const float* __restrict__ xg,
                              const float* __restrict__ Wl,   // 27*64*64
                              float* __restrict__ yg) {
    int np = g_npairs;
    if (np > MAXP) np = MAXP;
    long total = (long)np * 64;
    for (long idx = blockIdx.x * (long)blockDim.x + threadIdx.x; idx < total;
         idx += (long)gridDim.x * blockDim.x) {
        int p = (int)(idx >> 6);
        int c = (int)(idx & 63);
        int2 pr = g_pairs[p];
        int i = pr.x, j = pr.y >> 5, k = pr.y & 31;
        const float* xr = xg + (long)j * 64;
        const float* w = Wl + k * 4096 + c;
        float acc = 0.f;
        #pragma unroll
        for (int cin = 0; cin < 64; cin++) acc = fmaf(xr[cin], w[cin * 64], acc);
        atomicAdd(&yg[(long)i * 64 + c], acc);
    }
}

// ---------------- launch ----------------
extern "C" void kernel_launch(void* const* d_in, const int* in_sizes, int n_in,
                              void* d_out, int out_size) {
    const float* features = (const float*)d_in[0];
    const float* Ws       = (const float*)d_in[1];
    const int*   coors    = (const int*)d_in[2];
    float*       out      = (float*)d_out;

    int n = in_sizes[0] / 64;
    if (n > NPTS) n = NPTS;

    // Rulebook (layer-invariant)
    k_clear<<<HSZ / 4 / 256, 256>>>();
    k_insert<<<(n + 255) / 256, 256>>>(coors, n);
    k_pairs<<<(n + 127) / 128, 128>>>(coors, n);

    int gblocks = (n + TILE - 1) / TILE;
    const int PAIR_GRID = 1024, PAIR_BLK = 128;

    // Layer 0: features -> bufA
    k_gemm<<<gblocks, 128>>>(features, Ws + (0 * 27 + 13) * 4096, g_bufA, n);
    k_apply_pairs<<<PAIR_GRID, PAIR_BLK>>>(features, Ws + 0 * 27 * 4096, g_bufA);
    // Layer 1: bufA -> bufB
    k_gemm<<<gblocks, 128>>>(g_bufA, Ws + (1 * 27 + 13) * 4096, g_bufB, n);
    k_apply_pairs<<<PAIR_GRID, PAIR_BLK>>>(g_bufA, Ws + 1 * 27 * 4096, g_bufB);
    // Layer 2: bufB -> out
    k_gemm<<<gblocks, 128>>>(g_bufB, Ws + (2 * 27 + 13) * 4096, out, n);
    k_apply_pairs<<<PAIR_GRID, PAIR_BLK>>>(g_bufB, Ws + 2 * 27 * 4096, out);
}